// round 13
// baseline (speedup 1.0000x reference)
#include <cuda_runtime.h>
#include <cuda_bf16.h>
#include <cuda_fp16.h>
#include <cstdint>

#define BB 8
#define TT 2048
#define EE 1024
#define HS 64
#define NTOT 192   // q(64) | k(64) | v(64)
#define ROWS (BB * TT)

// Preconverted operands (written by qkv epilogue)
__device__ __nv_bfloat16 g_qh[ROWS * HS];   // Q hi, pre-scaled 0.125, [B*T][64]
__device__ __nv_bfloat16 g_ql[ROWS * HS];
__device__ __nv_bfloat16 g_kh[ROWS * HS];   // K hi [B*T][64]
__device__ __nv_bfloat16 g_kl[ROWS * HS];
__device__ __half        g_vth[BB * HS * TT];  // V transposed [B][64h][2048t], fp16
// Weights fp16 hi/lo of (32*W)
__device__ __half g_Wh[NTOT * EE];
__device__ __half g_Wl[NTOT * EE];

// ---------------------------------------------------------------------------
// Helpers
// ---------------------------------------------------------------------------
__device__ __forceinline__ uint32_t smem_u32(const void* p) {
    uint32_t a;
    asm("{ .reg .u64 t; cvta.to.shared.u64 t, %1; cvt.u32.u64 %0, t; }"
        : "=r"(a) : "l"(p));
    return a;
}

__device__ __forceinline__ void cp16(uint32_t dst, const void* src) {
    asm volatile("cp.async.cg.shared.global [%0], [%1], 16;"
                 :: "r"(dst), "l"(src));
}

// bf16 mma, fp32 accum
__device__ __forceinline__ void mma16816(float* c, const uint32_t* a,
                                         const uint32_t* b) {
    asm volatile(
        "mma.sync.aligned.m16n8k16.row.col.f32.bf16.bf16.f32 "
        "{%0,%1,%2,%3}, {%4,%5,%6,%7}, {%8,%9}, {%0,%1,%2,%3};"
        : "+f"(c[0]), "+f"(c[1]), "+f"(c[2]), "+f"(c[3])
        : "r"(a[0]), "r"(a[1]), "r"(a[2]), "r"(a[3]), "r"(b[0]), "r"(b[1]));
}

// fp16 mma, fp32 accum
__device__ __forceinline__ void mma16816h(float* c, const uint32_t* a,
                                          const uint32_t* b) {
    asm volatile(
        "mma.sync.aligned.m16n8k16.row.col.f32.f16.f16.f32 "
        "{%0,%1,%2,%3}, {%4,%5,%6,%7}, {%8,%9}, {%0,%1,%2,%3};"
        : "+f"(c[0]), "+f"(c[1]), "+f"(c[2]), "+f"(c[3])
        : "r"(a[0]), "r"(a[1]), "r"(a[2]), "r"(a[3]), "r"(b[0]), "r"(b[1]));
}

// ldmatrix x4 (non-trans, b16)
__device__ __forceinline__ void ldmx4(uint32_t* r, uint32_t addr) {
    asm volatile(
        "ldmatrix.sync.aligned.m8n8.x4.shared.b16 {%0,%1,%2,%3}, [%4];"
        : "=r"(r[0]), "=r"(r[1]), "=r"(r[2]), "=r"(r[3]) : "r"(addr));
}

// ---------------------------------------------------------------------------
// Kernel 0: convert concat(Wq,Wk,Wv)*32 fp32 -> fp16 hi/lo, [192][1024]
// ---------------------------------------------------------------------------
__global__ __launch_bounds__(256) void w_convert_kernel(
    const float* __restrict__ Wq, const float* __restrict__ Wk,
    const float* __restrict__ Wv)
{
    int idx = blockIdx.x * 256 + threadIdx.x;
    int e4 = idx * 4;
    int n = e4 >> 10;
    int c = e4 & 1023;
    const float* src = (n < 64) ? &Wq[n * 1024 + c]
                     : (n < 128) ? &Wk[(n - 64) * 1024 + c]
                     : &Wv[(n - 128) * 1024 + c];
    float4 v = *(const float4*)src;
    float vs[4] = {v.x * 32.0f, v.y * 32.0f, v.z * 32.0f, v.w * 32.0f};
    __half h[4], l[4];
    #pragma unroll
    for (int e = 0; e < 4; e++) {
        h[e] = __float2half_rn(vs[e]);
        l[e] = __float2half_rn(vs[e] - __half2float(h[e]));
    }
    *(uint2*)&g_Wh[e4] = *(uint2*)h;
    *(uint2*)&g_Wl[e4] = *(uint2*)l;
}

// ---------------------------------------------------------------------------
// Kernel 1: QKV projection, fp16 2-term mma (exact R7).
// ---------------------------------------------------------------------------
#define ASTRIDE 80
#define BOFF  10240
#define STAGE 34816
#define SMEM_QKV (2 * STAGE)

__global__ void __launch_bounds__(256) qkv_mma_kernel(
    const float* __restrict__ X,
    const float* __restrict__ bq, const float* __restrict__ bk,
    const float* __restrict__ bv)
{
    extern __shared__ __align__(128) char sm[];
    const uint32_t smb = smem_u32(sm);
    const int tid = threadIdx.x;
    const int lid = tid & 31;
    const int wid = tid >> 5;
    const int wm  = wid >> 2;
    const int wn  = wid & 3;
    const int lg  = lid >> 2;
    const int lt  = lid & 3;
    const int m0  = blockIdx.x * 128;
    const int arow = tid >> 1;
    const int akh  = tid & 1;

    float acc[4][6][4];
    #pragma unroll
    for (int t = 0; t < 4; t++)
        #pragma unroll
        for (int u = 0; u < 6; u++)
            #pragma unroll
            for (int r = 0; r < 4; r++) acc[t][u][r] = 0.0f;

    float4 xr[4];

    {
        const float* xp = &X[(size_t)(m0 + arow) * EE + akh * 16];
        #pragma unroll
        for (int p = 0; p < 4; p++) xr[p] = *(const float4*)&xp[p * 4];
        #pragma unroll
        for (int j = 0; j < 6; j++) {
            int idx = j * 256 + tid;
            int n = idx >> 3, u = idx & 7;
            int kg = u & 3, wh = u >> 2;
            const __half* s = (wh ? g_Wl : g_Wh) + n * EE + kg * 8;
            cp16(smb + BOFF + n * 128 + ((u ^ (n & 7)) * 16), s);
        }
        asm volatile("cp.async.commit_group;");
        {
            __half2 hh[8];
            #pragma unroll
            for (int p = 0; p < 4; p++) {
                hh[2 * p]     = __floats2half2_rn(xr[p].x, xr[p].y);
                hh[2 * p + 1] = __floats2half2_rn(xr[p].z, xr[p].w);
            }
            *(uint4*)(sm + arow * ASTRIDE + akh * 32)      = *(uint4*)&hh[0];
            *(uint4*)(sm + arow * ASTRIDE + akh * 32 + 16) = *(uint4*)&hh[4];
        }
        asm volatile("cp.async.wait_group 0;");
        __syncthreads();
    }

    for (int c = 0; c < 32; c++) {
        const int cb = c & 1;
        const int nb = (c + 1) & 1;
        if (c < 31) {
            const int k0 = (c + 1) * 32;
            const float* xp = &X[(size_t)(m0 + arow) * EE + k0 + akh * 16];
            #pragma unroll
            for (int p = 0; p < 4; p++) xr[p] = *(const float4*)&xp[p * 4];
            #pragma unroll
            for (int j = 0; j < 6; j++) {
                int idx = j * 256 + tid;
                int n = idx >> 3, u = idx & 7;
                int kg = u & 3, wh = u >> 2;
                const __half* s = (wh ? g_Wl : g_Wh) + n * EE + k0 + kg * 8;
                cp16(smb + nb * STAGE + BOFF + n * 128 + ((u ^ (n & 7)) * 16), s);
            }
            asm volatile("cp.async.commit_group;");
        }

        const char* ab = sm + cb * STAGE;
        const char* bb = ab + BOFF;
        #pragma unroll
        for (int h = 0; h < 2; h++) {
            uint32_t af[4][4], bfh[6][2], bfl[6][2];
            #pragma unroll
            for (int t = 0; t < 4; t++) {
                int r  = wm * 64 + t * 16 + lg;
                int r8 = r + 8;
                af[t][0] = *(const uint32_t*)(ab + r  * ASTRIDE + (2 * h) * 16 + lt * 4);
                af[t][1] = *(const uint32_t*)(ab + r8 * ASTRIDE + (2 * h) * 16 + lt * 4);
                af[t][2] = *(const uint32_t*)(ab + r  * ASTRIDE + (2 * h + 1) * 16 + lt * 4);
                af[t][3] = *(const uint32_t*)(ab + r8 * ASTRIDE + (2 * h + 1) * 16 + lt * 4);
            }
            #pragma unroll
            for (int u = 0; u < 6; u++) {
                int n = wn * 48 + u * 8 + lg;
                int kg0 = 2 * h, kg1 = 2 * h + 1;
                bfh[u][0] = *(const uint32_t*)(bb + n * 128 + ((kg0 ^ (n & 7)) * 16) + lt * 4);
                bfh[u][1] = *(const uint32_t*)(bb + n * 128 + ((kg1 ^ (n & 7)) * 16) + lt * 4);
                bfl[u][0] = *(const uint32_t*)(bb + n * 128 + (((kg0 | 4) ^ (n & 7)) * 16) + lt * 4);
                bfl[u][1] = *(const uint32_t*)(bb + n * 128 + (((kg1 | 4) ^ (n & 7)) * 16) + lt * 4);
            }
            #pragma unroll
            for (int t = 0; t < 4; t++)
                #pragma unroll
                for (int u = 0; u < 6; u++)
                    mma16816h(acc[t][u], af[t], bfh[u]);
            #pragma unroll
            for (int t = 0; t < 4; t++)
                #pragma unroll
                for (int u = 0; u < 6; u++)
                    mma16816h(acc[t][u], af[t], bfl[u]);
        }

        if (c < 31) {
            __half2 hh[8];
            #pragma unroll
            for (int p = 0; p < 4; p++) {
                hh[2 * p]     = __floats2half2_rn(xr[p].x, xr[p].y);
                hh[2 * p + 1] = __floats2half2_rn(xr[p].z, xr[p].w);
            }
            *(uint4*)(sm + nb * STAGE + arow * ASTRIDE + akh * 32)      = *(uint4*)&hh[0];
            *(uint4*)(sm + nb * STAGE + arow * ASTRIDE + akh * 32 + 16) = *(uint4*)&hh[4];
            asm volatile("cp.async.wait_group 0;");
        }
        __syncthreads();
    }

    // ---- epilogue: acc/32 + bias; Q/K -> bf16 hi/lo; V -> fp16 via smem T
    __half* VtSh = (__half*)sm;                  // [64h][128 rl]

    #pragma unroll
    for (int t = 0; t < 4; t++) {
        int rl = wm * 64 + t * 16 + lg;
        size_t rg = (size_t)(m0 + rl);
        #pragma unroll
        for (int u = 0; u < 6; u++) {
            int n = wn * 48 + u * 8 + lt * 2;
            const float* barr; int col; int kind;
            if (n < 64)       { col = n;       barr = bq; kind = 0; }
            else if (n < 128) { col = n - 64;  barr = bk; kind = 1; }
            else              { col = n - 128; barr = bv; kind = 2; }
            float b0 = __ldg(&barr[col]), b1 = __ldg(&barr[col + 1]);
            float v00 = acc[t][u][0] * 0.03125f + b0;
            float v01 = acc[t][u][1] * 0.03125f + b1;
            float v10 = acc[t][u][2] * 0.03125f + b0;
            float v11 = acc[t][u][3] * 0.03125f + b1;
            if (kind == 0) {
                v00 *= 0.125f; v01 *= 0.125f; v10 *= 0.125f; v11 *= 0.125f;
            }
            if (kind < 2) {
                __nv_bfloat16* dh = kind ? g_kh : g_qh;
                __nv_bfloat16* dl = kind ? g_kl : g_ql;
                __nv_bfloat162 h0p = __floats2bfloat162_rn(v00, v01);
                float2 f0 = __bfloat1622float2(h0p);
                __nv_bfloat162 l0p = __floats2bfloat162_rn(v00 - f0.x, v01 - f0.y);
                __nv_bfloat162 h1p = __floats2bfloat162_rn(v10, v11);
                float2 f1 = __bfloat1622float2(h1p);
                __nv_bfloat162 l1p = __floats2bfloat162_rn(v10 - f1.x, v11 - f1.y);
                *(uint32_t*)&dh[rg * HS + col]       = *(uint32_t*)&h0p;
                *(uint32_t*)&dl[rg * HS + col]       = *(uint32_t*)&l0p;
                *(uint32_t*)&dh[(rg + 8) * HS + col] = *(uint32_t*)&h1p;
                *(uint32_t*)&dl[(rg + 8) * HS + col] = *(uint32_t*)&l1p;
            } else {
                VtSh[col * 128 + rl]           = __float2half_rn(v00);
                VtSh[(col + 1) * 128 + rl]     = __float2half_rn(v01);
                VtSh[col * 128 + rl + 8]       = __float2half_rn(v10);
                VtSh[(col + 1) * 128 + rl + 8] = __float2half_rn(v11);
            }
        }
    }
    __syncthreads();
    {
        int bbb = m0 >> 11, t0 = m0 & 2047;
        #pragma unroll
        for (int q = 0; q < 4; q++) {
            int idx = q * 256 + tid;
            int h = idx >> 4, cc = idx & 15;
            __half* dst = g_vth + ((size_t)(bbb * HS + h)) * TT + t0 + cc * 8;
            *(uint4*)dst = *(const uint4*)(VtSh + h * 128 + cc * 8);
        }
    }
}

// ---------------------------------------------------------------------------
// Kernel 2: causal flash attention.  R7 core, but the two key-split halves
// of each tile pair live in ONE 256-thread CTA as two warp-groups (group g
// = key-parity g), each with its own double-buffer pair and group-scoped
// named barriers.  Merge is done in smem at the tile tail — no combine
// kernel, no global partials.  Grid (16, 8) = 128 CTAs, 1/SM.
// ---------------------------------------------------------------------------
#define STG 27648
#define SMEM_ATTN (4 * STG)

#define GBAR() asm volatile("bar.sync %0, 128;" :: "r"(g + 1) : "memory")

#define LOADSTAGE(st_, kt_) do {                                              \
    uint32_t sb_ = smb + (uint32_t)(g * 2 + (st_)) * STG;                     \
    size_t kbase_ = ((size_t)b * TT + (size_t)(kt_) * 64) * HS;               \
    size_t vbase_ = (size_t)b * (HS * TT) + (size_t)(kt_) * 64;               \
    _Pragma("unroll")                                                         \
    for (int q_ = 0; q_ < 4; q_++) {                                          \
        int idx_ = q_ * 128 + tg;                                             \
        int r_ = idx_ >> 3, c_ = idx_ & 7;                                    \
        cp16(sb_ + r_ * 144 + c_ * 16,          g_kh + kbase_ + r_ * HS + c_ * 8);  \
        cp16(sb_ + 9216 + r_ * 144 + c_ * 16,   g_kl + kbase_ + r_ * HS + c_ * 8);  \
        cp16(sb_ + 18432 + r_ * 144 + c_ * 16,  g_vth + vbase_ + (size_t)r_ * TT + c_ * 8); \
    }                                                                         \
    asm volatile("cp.async.commit_group;");                                   \
} while (0)

__global__ void __launch_bounds__(256) attn_mma_kernel(float* __restrict__ out)
{
    extern __shared__ __align__(16) char smd[];
    const uint32_t smb = smem_u32(smd);
    const int pairI = blockIdx.x;          // 0..15
    const int b = blockIdx.y;
    const int tid  = threadIdx.x;
    const int g    = tid >> 7;             // warp-group = key parity
    const int tg   = tid & 127;            // tid within group
    const int lane = tid & 31;
    const int w    = tg >> 5;              // warp within group: 0..3
    const int lg   = lane >> 2;
    const int lt   = lane & 3;
    const int wrow = w * 16;

    const int gg = lane >> 3, ii = lane & 7;
    const uint32_t lih =
        (uint32_t)((((gg >> 1) * 8) + ii) * 144 + (gg & 1) * 16);

    // smem merge area (overlays group 0's stage buffers; only used after
    // both groups' compute loops for the tile are complete)
    float* mO = (float*)smd;               // [64][68] padded
    float* mM = (float*)(smd + 17408);     // [64]
    float* mL = (float*)(smd + 17664);     // [64]

    for (int tt = 0; tt < 2; tt++) {
        const int qt = tt ? (31 - pairI) : pairI;
        const int q0 = qt * 64;

        // Q fragments straight from global bf16 (pre-scaled, pre-split)
        uint32_t qh[4][4], ql[4][4];
        {
            const size_t qb = ((size_t)b * TT + q0) * HS;
            #pragma unroll
            for (int kk = 0; kk < 4; kk++) {
                int h0 = kk * 16 + 2 * lt;
                qh[kk][0] = *(const uint32_t*)&g_qh[qb + (wrow + lg) * HS + h0];
                qh[kk][1] = *(const uint32_t*)&g_qh[qb + (wrow + lg + 8) * HS + h0];
                qh[kk][2] = *(const uint32_t*)&g_qh[qb + (wrow + lg) * HS + h0 + 8];
                qh[kk][3] = *(const uint32_t*)&g_qh[qb + (wrow + lg + 8) * HS + h0 + 8];
                ql[kk][0] = *(const uint32_t*)&g_ql[qb + (wrow + lg) * HS + h0];
                ql[kk][1] = *(const uint32_t*)&g_ql[qb + (wrow + lg + 8) * HS + h0];
                ql[kk][2] = *(const uint32_t*)&g_ql[qb + (wrow + lg) * HS + h0 + 8];
                ql[kk][3] = *(const uint32_t*)&g_ql[qb + (wrow + lg + 8) * HS + h0 + 8];
            }
        }

        float O[8][4];
        #pragma unroll
        for (int j = 0; j < 8; j++)
            #pragma unroll
            for (int e = 0; e < 4; e++) O[j][e] = 0.0f;
        float m0 = -1e30f, m1 = -1e30f, l0 = 0.0f, l1 = 0.0f;

        const int p = g;
        const int nkt = (qt >= p) ? (((qt - p) >> 1) + 1) : 0;

        if (nkt > 0) LOADSTAGE(0, p);

        for (int i = 0; i < nkt; i++) {
            const int kt = p + 2 * i;
            const int st = i & 1;
            if (i) GBAR();               // compute i-1 done before buf reuse
            if (i + 1 < nkt) {
                LOADSTAGE(st ^ 1, kt + 2);
                asm volatile("cp.async.wait_group 1;");
            } else {
                asm volatile("cp.async.wait_group 0;");
            }
            GBAR();

            const uint32_t smKh = smb + (uint32_t)(g * 2 + st) * STG;
            const uint32_t smKl = smKh + 9216;
            const uint32_t smVh = smKh + 18432;

            // ---- S = Q K^T (bf16 3-term), B-frags via ldmatrix.x4
            float s[8][4];
            #pragma unroll
            for (int j = 0; j < 8; j++)
                #pragma unroll
                for (int e = 0; e < 4; e++) s[j][e] = 0.0f;

            #pragma unroll
            for (int kk = 0; kk < 4; kk++) {
                #pragma unroll
                for (int jp = 0; jp < 4; jp++) {
                    uint32_t bh[4], bl[4];
                    ldmx4(bh, smKh + lih + jp * 2304 + kk * 32);
                    ldmx4(bl, smKl + lih + jp * 2304 + kk * 32);
                    mma16816(s[2 * jp],     qh[kk], &bh[0]);
                    mma16816(s[2 * jp],     qh[kk], &bl[0]);
                    mma16816(s[2 * jp],     ql[kk], &bh[0]);
                    mma16816(s[2 * jp + 1], qh[kk], &bh[2]);
                    mma16816(s[2 * jp + 1], qh[kk], &bl[2]);
                    mma16816(s[2 * jp + 1], ql[kk], &bh[2]);
                }
            }

            // ---- causal mask (diagonal tile only)
            if (kt == qt) {
                #pragma unroll
                for (int j = 0; j < 8; j++) {
                    int lc = j * 8 + 2 * lt;
                    int r0 = wrow + lg, r1 = r0 + 8;
                    if (lc > r0)     s[j][0] = -1e30f;
                    if (lc + 1 > r0) s[j][1] = -1e30f;
                    if (lc > r1)     s[j][2] = -1e30f;
                    if (lc + 1 > r1) s[j][3] = -1e30f;
                }
            }

            // ---- online softmax
            {
                float mx0 = -1e30f, mx1 = -1e30f;
                #pragma unroll
                for (int j = 0; j < 8; j++) {
                    mx0 = fmaxf(mx0, fmaxf(s[j][0], s[j][1]));
                    mx1 = fmaxf(mx1, fmaxf(s[j][2], s[j][3]));
                }
                #pragma unroll
                for (int o = 1; o <= 2; o <<= 1) {
                    mx0 = fmaxf(mx0, __shfl_xor_sync(0xffffffffu, mx0, o));
                    mx1 = fmaxf(mx1, __shfl_xor_sync(0xffffffffu, mx1, o));
                }
                float mn0 = fmaxf(m0, mx0), mn1 = fmaxf(m1, mx1);
                float al0 = __expf(m0 - mn0), al1 = __expf(m1 - mn1);
                float sum0 = 0.0f, sum1 = 0.0f;
                #pragma unroll
                for (int j = 0; j < 8; j++) {
                    s[j][0] = __expf(s[j][0] - mn0);
                    s[j][1] = __expf(s[j][1] - mn0);
                    s[j][2] = __expf(s[j][2] - mn1);
                    s[j][3] = __expf(s[j][3] - mn1);
                    sum0 += s[j][0] + s[j][1];
                    sum1 += s[j][2] + s[j][3];
                }
                #pragma unroll
                for (int o = 1; o <= 2; o <<= 1) {
                    sum0 += __shfl_xor_sync(0xffffffffu, sum0, o);
                    sum1 += __shfl_xor_sync(0xffffffffu, sum1, o);
                }
                l0 = l0 * al0 + sum0;
                l1 = l1 * al1 + sum1;
                m0 = mn0; m1 = mn1;
                #pragma unroll
                for (int j = 0; j < 8; j++) {
                    O[j][0] *= al0; O[j][1] *= al0;
                    O[j][2] *= al1; O[j][3] *= al1;
                }
            }

            // ---- pack P -> fp16
            uint32_t pp[8][2];
            #pragma unroll
            for (int j = 0; j < 8; j++) {
                __half2 a01 = __floats2half2_rn(s[j][0], s[j][1]);
                __half2 a23 = __floats2half2_rn(s[j][2], s[j][3]);
                pp[j][0] = *(uint32_t*)&a01;
                pp[j][1] = *(uint32_t*)&a23;
            }

            // ---- O += P @ V (fp16 single-term), V-frags via ldmatrix.x4
            #pragma unroll
            for (int jhp = 0; jhp < 4; jhp++) {
                #pragma unroll
                for (int kk = 0; kk < 4; kk++) {
                    uint32_t vh[4];
                    ldmx4(vh, smVh + lih + jhp * 2304 + kk * 32);
                    uint32_t aP[4] = {pp[2 * kk][0], pp[2 * kk][1],
                                      pp[2 * kk + 1][0], pp[2 * kk + 1][1]};
                    mma16816h(O[2 * jhp],     aP, &vh[0]);
                    mma16816h(O[2 * jhp + 1], aP, &vh[2]);
                }
            }
        }

        // ==== intra-CTA merge: group 0 dumps partial to smem, group 1
        //      merges with its registers and writes final output.
        __syncthreads();                 // both groups done computing tile tt
        if (g == 0) {
            int r = wrow + lg;
            #pragma unroll
            for (int jh = 0; jh < 8; jh++) {
                int hcol = jh * 8 + 2 * lt;
                *(float2*)&mO[r * 68 + hcol] = make_float2(O[jh][0], O[jh][1]);
                *(float2*)&mO[(r + 8) * 68 + hcol] = make_float2(O[jh][2], O[jh][3]);
            }
            if (lt == 0) {
                mM[r] = m0;     mL[r] = l0;
                mM[r + 8] = m1; mL[r + 8] = l1;
            }
        }
        __syncthreads();
        if (g == 1) {
            int r = wrow + lg;
            float mo0 = mM[r],     lo0 = mL[r];
            float mo1 = mM[r + 8], lo1 = mL[r + 8];
            float M0 = fmaxf(m0, mo0), M1 = fmaxf(m1, mo1);
            float wa = __expf(m0 - M0), wb = __expf(mo0 - M0);
            float wc = __expf(m1 - M1), wd = __expf(mo1 - M1);
            float inv0 = 1.0f / (wa * l0 + wb * lo0);
            float inv1 = 1.0f / (wc * l1 + wd * lo1);
            float* ob = out + ((size_t)b * TT + q0) * HS;
            #pragma unroll
            for (int jh = 0; jh < 8; jh++) {
                int hcol = jh * 8 + 2 * lt;
                float2 a = *(float2*)&mO[r * 68 + hcol];
                float2 c = *(float2*)&mO[(r + 8) * 68 + hcol];
                *(float2*)&ob[(size_t)r * HS + hcol] =
                    make_float2((wa * O[jh][0] + wb * a.x) * inv0,
                                (wa * O[jh][1] + wb * a.y) * inv0);
                *(float2*)&ob[(size_t)(r + 8) * HS + hcol] =
                    make_float2((wc * O[jh][2] + wd * c.x) * inv1,
                                (wc * O[jh][3] + wd * c.y) * inv1);
            }
        }
        __syncthreads();                 // merge reads done before buffers reused
    }
}

// ---------------------------------------------------------------------------
extern "C" void kernel_launch(void* const* d_in, const int* in_sizes, int n_in,
                              void* d_out, int out_size)
{
    const float* X  = (const float*)d_in[0];
    const float* Wq = (const float*)d_in[1];
    const float* bq = (const float*)d_in[2];
    const float* Wk = (const float*)d_in[3];
    const float* bk = (const float*)d_in[4];
    const float* Wv = (const float*)d_in[5];
    const float* bv = (const float*)d_in[6];
    float* out = (float*)d_out;

    static int attr_set = 0;
    if (!attr_set) {
        cudaFuncSetAttribute(qkv_mma_kernel,
                             cudaFuncAttributeMaxDynamicSharedMemorySize,
                             SMEM_QKV);
        cudaFuncSetAttribute(attn_mma_kernel,
                             cudaFuncAttributeMaxDynamicSharedMemorySize,
                             SMEM_ATTN);
        attr_set = 1;
    }

    w_convert_kernel<<<192, 256>>>(Wq, Wk, Wv);
    qkv_mma_kernel<<<128, 256, SMEM_QKV>>>(X, bq, bk, bv);

    dim3 g2(16, BB);                       // tile pairs x batches
    attn_mma_kernel<<<g2, 256, SMEM_ATTN>>>(out);
}

// round 14
// speedup vs baseline: 1.2016x; 1.2016x over previous
#include <cuda_runtime.h>
#include <cuda_bf16.h>
#include <cuda_fp16.h>
#include <cstdint>

#define BB 8
#define TT 2048
#define EE 1024
#define HS 64
#define NTOT 192   // q(64) | k(64) | v(64)
#define ROWS (BB * TT)
#define PSTRIDE (BB * TT * HS)

// Preconverted operands (written by qkv epilogue)
__device__ __nv_bfloat16 g_qh[ROWS * HS];   // Q hi, pre-scaled 0.125, [B*T][64]
__device__ __nv_bfloat16 g_ql[ROWS * HS];
__device__ __nv_bfloat16 g_kh[ROWS * HS];   // K hi [B*T][64]
__device__ __nv_bfloat16 g_kl[ROWS * HS];
__device__ __half        g_vth[BB * HS * TT];  // V transposed [B][64h][2048t], fp16
// Weights fp16 (single precision level)
__device__ __half g_Wh[NTOT * EE];
// Attention partials (2 key-split parts)
__device__ float g_pO[2 * PSTRIDE];
__device__ float g_pm[2 * ROWS];
__device__ float g_pl[2 * ROWS];

// ---------------------------------------------------------------------------
// Helpers
// ---------------------------------------------------------------------------
__device__ __forceinline__ uint32_t smem_u32(const void* p) {
    uint32_t a;
    asm("{ .reg .u64 t; cvta.to.shared.u64 t, %1; cvt.u32.u64 %0, t; }"
        : "=r"(a) : "l"(p));
    return a;
}

__device__ __forceinline__ void cp16(uint32_t dst, const void* src) {
    asm volatile("cp.async.cg.shared.global [%0], [%1], 16;"
                 :: "r"(dst), "l"(src));
}

// bf16 mma, fp32 accum
__device__ __forceinline__ void mma16816(float* c, const uint32_t* a,
                                         const uint32_t* b) {
    asm volatile(
        "mma.sync.aligned.m16n8k16.row.col.f32.bf16.bf16.f32 "
        "{%0,%1,%2,%3}, {%4,%5,%6,%7}, {%8,%9}, {%0,%1,%2,%3};"
        : "+f"(c[0]), "+f"(c[1]), "+f"(c[2]), "+f"(c[3])
        : "r"(a[0]), "r"(a[1]), "r"(a[2]), "r"(a[3]), "r"(b[0]), "r"(b[1]));
}

// fp16 mma, fp32 accum
__device__ __forceinline__ void mma16816h(float* c, const uint32_t* a,
                                          const uint32_t* b) {
    asm volatile(
        "mma.sync.aligned.m16n8k16.row.col.f32.f16.f16.f32 "
        "{%0,%1,%2,%3}, {%4,%5,%6,%7}, {%8,%9}, {%0,%1,%2,%3};"
        : "+f"(c[0]), "+f"(c[1]), "+f"(c[2]), "+f"(c[3])
        : "r"(a[0]), "r"(a[1]), "r"(a[2]), "r"(a[3]), "r"(b[0]), "r"(b[1]));
}

// ldmatrix x4 (non-trans, b16)
__device__ __forceinline__ void ldmx4(uint32_t* r, uint32_t addr) {
    asm volatile(
        "ldmatrix.sync.aligned.m8n8.x4.shared.b16 {%0,%1,%2,%3}, [%4];"
        : "=r"(r[0]), "=r"(r[1]), "=r"(r[2]), "=r"(r[3]) : "r"(addr));
}

// ---------------------------------------------------------------------------
// Kernel 0: convert concat(Wq,Wk,Wv) fp32 -> fp16, [192][1024]
// ---------------------------------------------------------------------------
__global__ __launch_bounds__(256) void w_convert_kernel(
    const float* __restrict__ Wq, const float* __restrict__ Wk,
    const float* __restrict__ Wv)
{
    int idx = blockIdx.x * 256 + threadIdx.x;
    int e4 = idx * 4;
    int n = e4 >> 10;
    int c = e4 & 1023;
    const float* src = (n < 64) ? &Wq[n * 1024 + c]
                     : (n < 128) ? &Wk[(n - 64) * 1024 + c]
                     : &Wv[(n - 128) * 1024 + c];
    float4 v = *(const float4*)src;
    __half h[4];
    h[0] = __float2half_rn(v.x);
    h[1] = __float2half_rn(v.y);
    h[2] = __float2half_rn(v.z);
    h[3] = __float2half_rn(v.w);
    *(uint2*)&g_Wh[e4] = *(uint2*)h;
}

// ---------------------------------------------------------------------------
// Kernel 1: QKV projection, fp16 single-term mma: X_fp16 * W_fp16.
// A stage: 128 rows x 32 fp16, 80B stride.  B stage: 192 rows x 32 fp16,
// 80B stride (20-bank stride -> all-32-banks-distinct frag loads).
// ---------------------------------------------------------------------------
#define ASTRIDE 80
#define BOFF  10240
#define STAGE 25600
#define SMEM_QKV (2 * STAGE)

__global__ void __launch_bounds__(256) qkv_mma_kernel(
    const float* __restrict__ X,
    const float* __restrict__ bq, const float* __restrict__ bk,
    const float* __restrict__ bv)
{
    extern __shared__ __align__(128) char sm[];
    const uint32_t smb = smem_u32(sm);
    const int tid = threadIdx.x;
    const int lid = tid & 31;
    const int wid = tid >> 5;
    const int wm  = wid >> 2;
    const int wn  = wid & 3;
    const int lg  = lid >> 2;
    const int lt  = lid & 3;
    const int m0  = blockIdx.x * 128;
    const int arow = tid >> 1;
    const int akh  = tid & 1;

    float acc[4][6][4];
    #pragma unroll
    for (int t = 0; t < 4; t++)
        #pragma unroll
        for (int u = 0; u < 6; u++)
            #pragma unroll
            for (int r = 0; r < 4; r++) acc[t][u][r] = 0.0f;

    float4 xr[4];

    // ---- prologue: chunk 0
    {
        const float* xp = &X[(size_t)(m0 + arow) * EE + akh * 16];
        #pragma unroll
        for (int p = 0; p < 4; p++) xr[p] = *(const float4*)&xp[p * 4];
        #pragma unroll
        for (int j = 0; j < 3; j++) {
            int idx = j * 256 + tid;          // 0..767
            int n = idx >> 2, u = idx & 3;
            cp16(smb + BOFF + n * 80 + u * 16, g_Wh + n * EE + u * 8);
        }
        asm volatile("cp.async.commit_group;");
        {
            __half2 hh[8];
            #pragma unroll
            for (int p = 0; p < 4; p++) {
                hh[2 * p]     = __floats2half2_rn(xr[p].x, xr[p].y);
                hh[2 * p + 1] = __floats2half2_rn(xr[p].z, xr[p].w);
            }
            *(uint4*)(sm + arow * ASTRIDE + akh * 32)      = *(uint4*)&hh[0];
            *(uint4*)(sm + arow * ASTRIDE + akh * 32 + 16) = *(uint4*)&hh[4];
        }
        asm volatile("cp.async.wait_group 0;");
        __syncthreads();
    }

    for (int c = 0; c < 32; c++) {
        const int cb = c & 1;
        const int nb = (c + 1) & 1;
        if (c < 31) {
            const int k0 = (c + 1) * 32;
            const float* xp = &X[(size_t)(m0 + arow) * EE + k0 + akh * 16];
            #pragma unroll
            for (int p = 0; p < 4; p++) xr[p] = *(const float4*)&xp[p * 4];
            #pragma unroll
            for (int j = 0; j < 3; j++) {
                int idx = j * 256 + tid;
                int n = idx >> 2, u = idx & 3;
                cp16(smb + nb * STAGE + BOFF + n * 80 + u * 16,
                     g_Wh + n * EE + k0 + u * 8);
            }
            asm volatile("cp.async.commit_group;");
        }

        // ---- compute chunk c (two k16 steps)
        const char* ab = sm + cb * STAGE;
        const char* bb = ab + BOFF;
        #pragma unroll
        for (int h = 0; h < 2; h++) {
            uint32_t af[4][4], bf[6][2];
            #pragma unroll
            for (int t = 0; t < 4; t++) {
                int r  = wm * 64 + t * 16 + lg;
                int r8 = r + 8;
                af[t][0] = *(const uint32_t*)(ab + r  * ASTRIDE + (2 * h) * 16 + lt * 4);
                af[t][1] = *(const uint32_t*)(ab + r8 * ASTRIDE + (2 * h) * 16 + lt * 4);
                af[t][2] = *(const uint32_t*)(ab + r  * ASTRIDE + (2 * h + 1) * 16 + lt * 4);
                af[t][3] = *(const uint32_t*)(ab + r8 * ASTRIDE + (2 * h + 1) * 16 + lt * 4);
            }
            #pragma unroll
            for (int u = 0; u < 6; u++) {
                int n = wn * 48 + u * 8 + lg;
                bf[u][0] = *(const uint32_t*)(bb + n * 80 + (2 * h) * 16 + lt * 4);
                bf[u][1] = *(const uint32_t*)(bb + n * 80 + (2 * h + 1) * 16 + lt * 4);
            }
            #pragma unroll
            for (int t = 0; t < 4; t++)
                #pragma unroll
                for (int u = 0; u < 6; u++)
                    mma16816h(acc[t][u], af[t], bf[u]);
        }

        if (c < 31) {
            __half2 hh[8];
            #pragma unroll
            for (int p = 0; p < 4; p++) {
                hh[2 * p]     = __floats2half2_rn(xr[p].x, xr[p].y);
                hh[2 * p + 1] = __floats2half2_rn(xr[p].z, xr[p].w);
            }
            *(uint4*)(sm + nb * STAGE + arow * ASTRIDE + akh * 32)      = *(uint4*)&hh[0];
            *(uint4*)(sm + nb * STAGE + arow * ASTRIDE + akh * 32 + 16) = *(uint4*)&hh[4];
            asm volatile("cp.async.wait_group 0;");
        }
        __syncthreads();
    }

    // ---- epilogue: + bias; Q/K -> bf16 hi/lo; V -> fp16 via smem T
    __half* VtSh = (__half*)sm;                  // [64h][128 rl]

    #pragma unroll
    for (int t = 0; t < 4; t++) {
        int rl = wm * 64 + t * 16 + lg;
        size_t rg = (size_t)(m0 + rl);
        #pragma unroll
        for (int u = 0; u < 6; u++) {
            int n = wn * 48 + u * 8 + lt * 2;
            const float* barr; int col; int kind;
            if (n < 64)       { col = n;       barr = bq; kind = 0; }
            else if (n < 128) { col = n - 64;  barr = bk; kind = 1; }
            else              { col = n - 128; barr = bv; kind = 2; }
            float b0 = __ldg(&barr[col]), b1 = __ldg(&barr[col + 1]);
            float v00 = acc[t][u][0] + b0;
            float v01 = acc[t][u][1] + b1;
            float v10 = acc[t][u][2] + b0;
            float v11 = acc[t][u][3] + b1;
            if (kind == 0) {
                v00 *= 0.125f; v01 *= 0.125f; v10 *= 0.125f; v11 *= 0.125f;
            }
            if (kind < 2) {
                __nv_bfloat16* dh = kind ? g_kh : g_qh;
                __nv_bfloat16* dl = kind ? g_kl : g_ql;
                __nv_bfloat162 h0p = __floats2bfloat162_rn(v00, v01);
                float2 f0 = __bfloat1622float2(h0p);
                __nv_bfloat162 l0p = __floats2bfloat162_rn(v00 - f0.x, v01 - f0.y);
                __nv_bfloat162 h1p = __floats2bfloat162_rn(v10, v11);
                float2 f1 = __bfloat1622float2(h1p);
                __nv_bfloat162 l1p = __floats2bfloat162_rn(v10 - f1.x, v11 - f1.y);
                *(uint32_t*)&dh[rg * HS + col]       = *(uint32_t*)&h0p;
                *(uint32_t*)&dl[rg * HS + col]       = *(uint32_t*)&l0p;
                *(uint32_t*)&dh[(rg + 8) * HS + col] = *(uint32_t*)&h1p;
                *(uint32_t*)&dl[(rg + 8) * HS + col] = *(uint32_t*)&l1p;
            } else {
                VtSh[col * 128 + rl]           = __float2half_rn(v00);
                VtSh[(col + 1) * 128 + rl]     = __float2half_rn(v01);
                VtSh[col * 128 + rl + 8]       = __float2half_rn(v10);
                VtSh[(col + 1) * 128 + rl + 8] = __float2half_rn(v11);
            }
        }
    }
    __syncthreads();
    {
        int bbb = m0 >> 11, t0 = m0 & 2047;
        #pragma unroll
        for (int q = 0; q < 4; q++) {
            int idx = q * 256 + tid;
            int h = idx >> 4, cc = idx & 15;
            __half* dst = g_vth + ((size_t)(bbb * HS + h)) * TT + t0 + cc * 8;
            *(uint4*)dst = *(const uint4*)(VtSh + h * 128 + cc * 8);
        }
    }
}

// ---------------------------------------------------------------------------
// Kernel 2: causal flash attention (byte-exact R7).
// ---------------------------------------------------------------------------
#define STG 27648

#define LOADSTAGE(st_, kt_) do {                                              \
    uint32_t sb_ = smb + (st_) * STG;                                         \
    size_t kbase_ = ((size_t)b * TT + (size_t)(kt_) * 64) * HS;               \
    size_t vbase_ = (size_t)b * (HS * TT) + (size_t)(kt_) * 64;               \
    _Pragma("unroll")                                                         \
    for (int q_ = 0; q_ < 4; q_++) {                                          \
        int idx_ = q_ * 128 + tid;                                            \
        int r_ = idx_ >> 3, c_ = idx_ & 7;                                    \
        cp16(sb_ + r_ * 144 + c_ * 16,          g_kh + kbase_ + r_ * HS + c_ * 8);  \
        cp16(sb_ + 9216 + r_ * 144 + c_ * 16,   g_kl + kbase_ + r_ * HS + c_ * 8);  \
        cp16(sb_ + 18432 + r_ * 144 + c_ * 16,  g_vth + vbase_ + (size_t)r_ * TT + c_ * 8); \
    }                                                                         \
    asm volatile("cp.async.commit_group;");                                   \
} while (0)

__global__ void __launch_bounds__(128) attn_mma_kernel()
{
    extern __shared__ __align__(16) char smd[];
    const uint32_t smb = smem_u32(smd);
    const int pairI = blockIdx.x >> 1;
    const int p = blockIdx.x & 1;
    const int b = blockIdx.y;
    const int tid  = threadIdx.x;
    const int lane = tid & 31;
    const int w    = tid >> 5;
    const int lg   = lane >> 2;
    const int lt   = lane & 3;
    const int wrow = w * 16;

    const int gg = lane >> 3, ii = lane & 7;
    const uint32_t lih =
        (uint32_t)((((gg >> 1) * 8) + ii) * 144 + (gg & 1) * 16);

    for (int tt = 0; tt < 2; tt++) {
        const int qt = tt ? (31 - pairI) : pairI;
        const int q0 = qt * 64;

        // Q fragments straight from global bf16 (pre-scaled, pre-split)
        uint32_t qh[4][4], ql[4][4];
        {
            const size_t qb = ((size_t)b * TT + q0) * HS;
            #pragma unroll
            for (int kk = 0; kk < 4; kk++) {
                int h0 = kk * 16 + 2 * lt;
                qh[kk][0] = *(const uint32_t*)&g_qh[qb + (wrow + lg) * HS + h0];
                qh[kk][1] = *(const uint32_t*)&g_qh[qb + (wrow + lg + 8) * HS + h0];
                qh[kk][2] = *(const uint32_t*)&g_qh[qb + (wrow + lg) * HS + h0 + 8];
                qh[kk][3] = *(const uint32_t*)&g_qh[qb + (wrow + lg + 8) * HS + h0 + 8];
                ql[kk][0] = *(const uint32_t*)&g_ql[qb + (wrow + lg) * HS + h0];
                ql[kk][1] = *(const uint32_t*)&g_ql[qb + (wrow + lg + 8) * HS + h0];
                ql[kk][2] = *(const uint32_t*)&g_ql[qb + (wrow + lg) * HS + h0 + 8];
                ql[kk][3] = *(const uint32_t*)&g_ql[qb + (wrow + lg + 8) * HS + h0 + 8];
            }
        }

        float O[8][4];
        #pragma unroll
        for (int j = 0; j < 8; j++)
            #pragma unroll
            for (int e = 0; e < 4; e++) O[j][e] = 0.0f;
        float m0 = -1e30f, m1 = -1e30f, l0 = 0.0f, l1 = 0.0f;

        const int nkt = (qt >= p) ? (((qt - p) >> 1) + 1) : 0;

        __syncthreads();                 // stage buffers free before reuse
        if (nkt > 0) LOADSTAGE(0, p);

        for (int i = 0; i < nkt; i++) {
            const int kt = p + 2 * i;
            const int st = i & 1;
            if (i) __syncthreads();      // compute i-1 done before buf reuse
            if (i + 1 < nkt) {
                LOADSTAGE(st ^ 1, kt + 2);
                asm volatile("cp.async.wait_group 1;");
            } else {
                asm volatile("cp.async.wait_group 0;");
            }
            __syncthreads();

            const uint32_t smKh = smb + st * STG;
            const uint32_t smKl = smKh + 9216;
            const uint32_t smVh = smKh + 18432;

            // ---- S = Q K^T (bf16 3-term), B-frags via ldmatrix.x4
            float s[8][4];
            #pragma unroll
            for (int j = 0; j < 8; j++)
                #pragma unroll
                for (int e = 0; e < 4; e++) s[j][e] = 0.0f;

            #pragma unroll
            for (int kk = 0; kk < 4; kk++) {
                #pragma unroll
                for (int jp = 0; jp < 4; jp++) {
                    uint32_t bh[4], bl[4];
                    ldmx4(bh, smKh + lih + jp * 2304 + kk * 32);
                    ldmx4(bl, smKl + lih + jp * 2304 + kk * 32);
                    mma16816(s[2 * jp],     qh[kk], &bh[0]);
                    mma16816(s[2 * jp],     qh[kk], &bl[0]);
                    mma16816(s[2 * jp],     ql[kk], &bh[0]);
                    mma16816(s[2 * jp + 1], qh[kk], &bh[2]);
                    mma16816(s[2 * jp + 1], qh[kk], &bl[2]);
                    mma16816(s[2 * jp + 1], ql[kk], &bh[2]);
                }
            }

            // ---- causal mask (diagonal tile only)
            if (kt == qt) {
                #pragma unroll
                for (int j = 0; j < 8; j++) {
                    int lc = j * 8 + 2 * lt;
                    int r0 = wrow + lg, r1 = r0 + 8;
                    if (lc > r0)     s[j][0] = -1e30f;
                    if (lc + 1 > r0) s[j][1] = -1e30f;
                    if (lc > r1)     s[j][2] = -1e30f;
                    if (lc + 1 > r1) s[j][3] = -1e30f;
                }
            }

            // ---- online softmax
            {
                float mx0 = -1e30f, mx1 = -1e30f;
                #pragma unroll
                for (int j = 0; j < 8; j++) {
                    mx0 = fmaxf(mx0, fmaxf(s[j][0], s[j][1]));
                    mx1 = fmaxf(mx1, fmaxf(s[j][2], s[j][3]));
                }
                #pragma unroll
                for (int o = 1; o <= 2; o <<= 1) {
                    mx0 = fmaxf(mx0, __shfl_xor_sync(0xffffffffu, mx0, o));
                    mx1 = fmaxf(mx1, __shfl_xor_sync(0xffffffffu, mx1, o));
                }
                float mn0 = fmaxf(m0, mx0), mn1 = fmaxf(m1, mx1);
                float al0 = __expf(m0 - mn0), al1 = __expf(m1 - mn1);
                float sum0 = 0.0f, sum1 = 0.0f;
                #pragma unroll
                for (int j = 0; j < 8; j++) {
                    s[j][0] = __expf(s[j][0] - mn0);
                    s[j][1] = __expf(s[j][1] - mn0);
                    s[j][2] = __expf(s[j][2] - mn1);
                    s[j][3] = __expf(s[j][3] - mn1);
                    sum0 += s[j][0] + s[j][1];
                    sum1 += s[j][2] + s[j][3];
                }
                #pragma unroll
                for (int o = 1; o <= 2; o <<= 1) {
                    sum0 += __shfl_xor_sync(0xffffffffu, sum0, o);
                    sum1 += __shfl_xor_sync(0xffffffffu, sum1, o);
                }
                l0 = l0 * al0 + sum0;
                l1 = l1 * al1 + sum1;
                m0 = mn0; m1 = mn1;
                #pragma unroll
                for (int j = 0; j < 8; j++) {
                    O[j][0] *= al0; O[j][1] *= al0;
                    O[j][2] *= al1; O[j][3] *= al1;
                }
            }

            // ---- pack P -> fp16
            uint32_t pp[8][2];
            #pragma unroll
            for (int j = 0; j < 8; j++) {
                __half2 a01 = __floats2half2_rn(s[j][0], s[j][1]);
                __half2 a23 = __floats2half2_rn(s[j][2], s[j][3]);
                pp[j][0] = *(uint32_t*)&a01;
                pp[j][1] = *(uint32_t*)&a23;
            }

            // ---- O += P @ V (fp16 single-term), V-frags via ldmatrix.x4
            #pragma unroll
            for (int jhp = 0; jhp < 4; jhp++) {
                #pragma unroll
                for (int kk = 0; kk < 4; kk++) {
                    uint32_t vh[4];
                    ldmx4(vh, smVh + lih + jhp * 2304 + kk * 32);
                    uint32_t aP[4] = {pp[2 * kk][0], pp[2 * kk][1],
                                      pp[2 * kk + 1][0], pp[2 * kk + 1][1]};
                    mma16816h(O[2 * jhp],     aP, &vh[0]);
                    mma16816h(O[2 * jhp + 1], aP, &vh[2]);
                }
            }
        }

        // ---- write partial (unnormalized O, m, l)
        {
            const size_t r0 = (size_t)b * TT + q0 + wrow + lg;
            float* po = g_pO + (size_t)p * PSTRIDE;
            #pragma unroll
            for (int jh = 0; jh < 8; jh++) {
                int hcol = jh * 8 + 2 * lt;
                *(float2*)&po[r0 * HS + hcol] = make_float2(O[jh][0], O[jh][1]);
                *(float2*)&po[(r0 + 8) * HS + hcol] = make_float2(O[jh][2], O[jh][3]);
            }
            if (lt == 0) {
                g_pm[p * ROWS + r0] = m0;
                g_pl[p * ROWS + r0] = l0;
                g_pm[p * ROWS + r0 + 8] = m1;
                g_pl[p * ROWS + r0 + 8] = l1;
            }
        }
    }
}

// ---------------------------------------------------------------------------
// Kernel 3: merge the two key-split partials (exact R7).
// ---------------------------------------------------------------------------
__global__ __launch_bounds__(256) void combine_kernel(float* __restrict__ out)
{
    int idx = blockIdx.x * 256 + threadIdx.x;    // 262144 total
    int row = idx >> 4;
    int h4 = (idx & 15) * 4;
    float m0 = g_pm[row], m1 = g_pm[ROWS + row];
    float l0 = g_pl[row], l1 = g_pl[ROWS + row];
    float M = fmaxf(m0, m1);
    float w0 = __expf(m0 - M), w1 = __expf(m1 - M);
    float inv = 1.0f / (w0 * l0 + w1 * l1);
    float4 a = *(const float4*)&g_pO[(size_t)row * HS + h4];
    float4 c = *(const float4*)&g_pO[PSTRIDE + (size_t)row * HS + h4];
    float4 o;
    o.x = (w0 * a.x + w1 * c.x) * inv;
    o.y = (w0 * a.y + w1 * c.y) * inv;
    o.z = (w0 * a.z + w1 * c.z) * inv;
    o.w = (w0 * a.w + w1 * c.w) * inv;
    *(float4*)&out[(size_t)row * HS + h4] = o;
}

// ---------------------------------------------------------------------------
extern "C" void kernel_launch(void* const* d_in, const int* in_sizes, int n_in,
                              void* d_out, int out_size)
{
    const float* X  = (const float*)d_in[0];
    const float* Wq = (const float*)d_in[1];
    const float* bq = (const float*)d_in[2];
    const float* Wk = (const float*)d_in[3];
    const float* bk = (const float*)d_in[4];
    const float* Wv = (const float*)d_in[5];
    const float* bv = (const float*)d_in[6];
    float* out = (float*)d_out;

    static int attr_set = 0;
    if (!attr_set) {
        cudaFuncSetAttribute(qkv_mma_kernel,
                             cudaFuncAttributeMaxDynamicSharedMemorySize,
                             SMEM_QKV);
        cudaFuncSetAttribute(attn_mma_kernel,
                             cudaFuncAttributeMaxDynamicSharedMemorySize,
                             2 * STG);
        attr_set = 1;
    }

    w_convert_kernel<<<192, 256>>>(Wq, Wk, Wv);
    qkv_mma_kernel<<<128, 256, SMEM_QKV>>>(X, bq, bk, bv);

    dim3 g2(32, BB);                       // pairs x parts, batches
    attn_mma_kernel<<<g2, 128, 2 * STG>>>();

    combine_kernel<<<ROWS * HS / 4 / 256, 256>>>(out);
}

// round 15
// speedup vs baseline: 1.4150x; 1.1776x over previous
#include <cuda_runtime.h>
#include <cuda_bf16.h>
#include <cuda_fp16.h>
#include <cstdint>

#define BB 8
#define TT 2048
#define EE 1024
#define HS 64
#define NTOT 192   // q(64) | k(64) | v(64)
#define ROWS (BB * TT)
#define PSTRIDE (BB * TT * HS)

// Preconverted operands (written by qkv epilogue)
__device__ __half g_qh[ROWS * HS];          // Q fp16, pre-scaled 0.125
__device__ __half g_kh[ROWS * HS];          // K fp16 [B*T][64]
__device__ __half g_vth[BB * HS * TT];      // V transposed [B][64h][2048t], fp16
// Weights fp16 (single precision level)
__device__ __half g_Wh[NTOT * EE];
// Attention partials (2 key-split parts)
__device__ float g_pO[2 * PSTRIDE];
__device__ float g_pm[2 * ROWS];
__device__ float g_pl[2 * ROWS];

// ---------------------------------------------------------------------------
// Helpers
// ---------------------------------------------------------------------------
__device__ __forceinline__ uint32_t smem_u32(const void* p) {
    uint32_t a;
    asm("{ .reg .u64 t; cvta.to.shared.u64 t, %1; cvt.u32.u64 %0, t; }"
        : "=r"(a) : "l"(p));
    return a;
}

__device__ __forceinline__ void cp16(uint32_t dst, const void* src) {
    asm volatile("cp.async.cg.shared.global [%0], [%1], 16;"
                 :: "r"(dst), "l"(src));
}

// fp16 mma, fp32 accum
__device__ __forceinline__ void mma16816h(float* c, const uint32_t* a,
                                          const uint32_t* b) {
    asm volatile(
        "mma.sync.aligned.m16n8k16.row.col.f32.f16.f16.f32 "
        "{%0,%1,%2,%3}, {%4,%5,%6,%7}, {%8,%9}, {%0,%1,%2,%3};"
        : "+f"(c[0]), "+f"(c[1]), "+f"(c[2]), "+f"(c[3])
        : "r"(a[0]), "r"(a[1]), "r"(a[2]), "r"(a[3]), "r"(b[0]), "r"(b[1]));
}

// ldmatrix x4 (non-trans, b16)
__device__ __forceinline__ void ldmx4(uint32_t* r, uint32_t addr) {
    asm volatile(
        "ldmatrix.sync.aligned.m8n8.x4.shared.b16 {%0,%1,%2,%3}, [%4];"
        : "=r"(r[0]), "=r"(r[1]), "=r"(r[2]), "=r"(r[3]) : "r"(addr));
}

// ---------------------------------------------------------------------------
// Kernel 0: convert concat(Wq,Wk,Wv) fp32 -> fp16, [192][1024]
// ---------------------------------------------------------------------------
__global__ __launch_bounds__(256) void w_convert_kernel(
    const float* __restrict__ Wq, const float* __restrict__ Wk,
    const float* __restrict__ Wv)
{
    int idx = blockIdx.x * 256 + threadIdx.x;
    int e4 = idx * 4;
    int n = e4 >> 10;
    int c = e4 & 1023;
    const float* src = (n < 64) ? &Wq[n * 1024 + c]
                     : (n < 128) ? &Wk[(n - 64) * 1024 + c]
                     : &Wv[(n - 128) * 1024 + c];
    float4 v = *(const float4*)src;
    __half h[4];
    h[0] = __float2half_rn(v.x);
    h[1] = __float2half_rn(v.y);
    h[2] = __float2half_rn(v.z);
    h[3] = __float2half_rn(v.w);
    *(uint2*)&g_Wh[e4] = *(uint2*)h;
}

// ---------------------------------------------------------------------------
// Kernel 1: QKV projection, fp16 single-term mma (exact R14 mainloop).
// Epilogue now emits fp16 Q (scaled) and K.
// ---------------------------------------------------------------------------
#define ASTRIDE 80
#define BOFF  10240
#define STAGE 25600
#define SMEM_QKV (2 * STAGE)

__global__ void __launch_bounds__(256) qkv_mma_kernel(
    const float* __restrict__ X,
    const float* __restrict__ bq, const float* __restrict__ bk,
    const float* __restrict__ bv)
{
    extern __shared__ __align__(128) char sm[];
    const uint32_t smb = smem_u32(sm);
    const int tid = threadIdx.x;
    const int lid = tid & 31;
    const int wid = tid >> 5;
    const int wm  = wid >> 2;
    const int wn  = wid & 3;
    const int lg  = lid >> 2;
    const int lt  = lid & 3;
    const int m0  = blockIdx.x * 128;
    const int arow = tid >> 1;
    const int akh  = tid & 1;

    float acc[4][6][4];
    #pragma unroll
    for (int t = 0; t < 4; t++)
        #pragma unroll
        for (int u = 0; u < 6; u++)
            #pragma unroll
            for (int r = 0; r < 4; r++) acc[t][u][r] = 0.0f;

    float4 xr[4];

    // ---- prologue: chunk 0
    {
        const float* xp = &X[(size_t)(m0 + arow) * EE + akh * 16];
        #pragma unroll
        for (int p = 0; p < 4; p++) xr[p] = *(const float4*)&xp[p * 4];
        #pragma unroll
        for (int j = 0; j < 3; j++) {
            int idx = j * 256 + tid;          // 0..767
            int n = idx >> 2, u = idx & 3;
            cp16(smb + BOFF + n * 80 + u * 16, g_Wh + n * EE + u * 8);
        }
        asm volatile("cp.async.commit_group;");
        {
            __half2 hh[8];
            #pragma unroll
            for (int p = 0; p < 4; p++) {
                hh[2 * p]     = __floats2half2_rn(xr[p].x, xr[p].y);
                hh[2 * p + 1] = __floats2half2_rn(xr[p].z, xr[p].w);
            }
            *(uint4*)(sm + arow * ASTRIDE + akh * 32)      = *(uint4*)&hh[0];
            *(uint4*)(sm + arow * ASTRIDE + akh * 32 + 16) = *(uint4*)&hh[4];
        }
        asm volatile("cp.async.wait_group 0;");
        __syncthreads();
    }

    for (int c = 0; c < 32; c++) {
        const int cb = c & 1;
        const int nb = (c + 1) & 1;
        if (c < 31) {
            const int k0 = (c + 1) * 32;
            const float* xp = &X[(size_t)(m0 + arow) * EE + k0 + akh * 16];
            #pragma unroll
            for (int p = 0; p < 4; p++) xr[p] = *(const float4*)&xp[p * 4];
            #pragma unroll
            for (int j = 0; j < 3; j++) {
                int idx = j * 256 + tid;
                int n = idx >> 2, u = idx & 3;
                cp16(smb + nb * STAGE + BOFF + n * 80 + u * 16,
                     g_Wh + n * EE + k0 + u * 8);
            }
            asm volatile("cp.async.commit_group;");
        }

        // ---- compute chunk c (two k16 steps)
        const char* ab = sm + cb * STAGE;
        const char* bb = ab + BOFF;
        #pragma unroll
        for (int h = 0; h < 2; h++) {
            uint32_t af[4][4], bf[6][2];
            #pragma unroll
            for (int t = 0; t < 4; t++) {
                int r  = wm * 64 + t * 16 + lg;
                int r8 = r + 8;
                af[t][0] = *(const uint32_t*)(ab + r  * ASTRIDE + (2 * h) * 16 + lt * 4);
                af[t][1] = *(const uint32_t*)(ab + r8 * ASTRIDE + (2 * h) * 16 + lt * 4);
                af[t][2] = *(const uint32_t*)(ab + r  * ASTRIDE + (2 * h + 1) * 16 + lt * 4);
                af[t][3] = *(const uint32_t*)(ab + r8 * ASTRIDE + (2 * h + 1) * 16 + lt * 4);
            }
            #pragma unroll
            for (int u = 0; u < 6; u++) {
                int n = wn * 48 + u * 8 + lg;
                bf[u][0] = *(const uint32_t*)(bb + n * 80 + (2 * h) * 16 + lt * 4);
                bf[u][1] = *(const uint32_t*)(bb + n * 80 + (2 * h + 1) * 16 + lt * 4);
            }
            #pragma unroll
            for (int t = 0; t < 4; t++)
                #pragma unroll
                for (int u = 0; u < 6; u++)
                    mma16816h(acc[t][u], af[t], bf[u]);
        }

        if (c < 31) {
            __half2 hh[8];
            #pragma unroll
            for (int p = 0; p < 4; p++) {
                hh[2 * p]     = __floats2half2_rn(xr[p].x, xr[p].y);
                hh[2 * p + 1] = __floats2half2_rn(xr[p].z, xr[p].w);
            }
            *(uint4*)(sm + nb * STAGE + arow * ASTRIDE + akh * 32)      = *(uint4*)&hh[0];
            *(uint4*)(sm + nb * STAGE + arow * ASTRIDE + akh * 32 + 16) = *(uint4*)&hh[4];
            asm volatile("cp.async.wait_group 0;");
        }
        __syncthreads();
    }

    // ---- epilogue: + bias; Q/K -> fp16; V -> fp16 via smem transpose
    __half* VtSh = (__half*)sm;                  // [64h][128 rl]

    #pragma unroll
    for (int t = 0; t < 4; t++) {
        int rl = wm * 64 + t * 16 + lg;
        size_t rg = (size_t)(m0 + rl);
        #pragma unroll
        for (int u = 0; u < 6; u++) {
            int n = wn * 48 + u * 8 + lt * 2;
            const float* barr; int col; int kind;
            if (n < 64)       { col = n;       barr = bq; kind = 0; }
            else if (n < 128) { col = n - 64;  barr = bk; kind = 1; }
            else              { col = n - 128; barr = bv; kind = 2; }
            float b0 = __ldg(&barr[col]), b1 = __ldg(&barr[col + 1]);
            float v00 = acc[t][u][0] + b0;
            float v01 = acc[t][u][1] + b1;
            float v10 = acc[t][u][2] + b0;
            float v11 = acc[t][u][3] + b1;
            if (kind == 0) {
                v00 *= 0.125f; v01 *= 0.125f; v10 *= 0.125f; v11 *= 0.125f;
            }
            if (kind < 2) {
                __half* dh = kind ? g_kh : g_qh;
                __half2 h0p = __floats2half2_rn(v00, v01);
                __half2 h1p = __floats2half2_rn(v10, v11);
                *(uint32_t*)&dh[rg * HS + col]       = *(uint32_t*)&h0p;
                *(uint32_t*)&dh[(rg + 8) * HS + col] = *(uint32_t*)&h1p;
            } else {
                VtSh[col * 128 + rl]           = __float2half_rn(v00);
                VtSh[(col + 1) * 128 + rl]     = __float2half_rn(v01);
                VtSh[col * 128 + rl + 8]       = __float2half_rn(v10);
                VtSh[(col + 1) * 128 + rl + 8] = __float2half_rn(v11);
            }
        }
    }
    __syncthreads();
    {
        int bbb = m0 >> 11, t0 = m0 & 2047;
        #pragma unroll
        for (int q = 0; q < 4; q++) {
            int idx = q * 256 + tid;
            int h = idx >> 4, cc = idx & 15;
            __half* dst = g_vth + ((size_t)(bbb * HS + h)) * TT + t0 + cc * 8;
            *(uint4*)dst = *(const uint4*)(VtSh + h * 128 + cc * 8);
        }
    }
}

// ---------------------------------------------------------------------------
// Kernel 2: causal flash attention (R7/R14 structure), fp16 single-term on
// BOTH S=QK^T and O=PV.  Stage: K[64x144B] + V[64x144B] = 18432B, x2.
// ---------------------------------------------------------------------------
#define STG 18432

#define LOADSTAGE(st_, kt_) do {                                              \
    uint32_t sb_ = smb + (st_) * STG;                                         \
    size_t kbase_ = ((size_t)b * TT + (size_t)(kt_) * 64) * HS;               \
    size_t vbase_ = (size_t)b * (HS * TT) + (size_t)(kt_) * 64;               \
    _Pragma("unroll")                                                         \
    for (int q_ = 0; q_ < 4; q_++) {                                          \
        int idx_ = q_ * 128 + tid;                                            \
        int r_ = idx_ >> 3, c_ = idx_ & 7;                                    \
        cp16(sb_ + r_ * 144 + c_ * 16,         g_kh + kbase_ + r_ * HS + c_ * 8);  \
        cp16(sb_ + 9216 + r_ * 144 + c_ * 16,  g_vth + vbase_ + (size_t)r_ * TT + c_ * 8); \
    }                                                                         \
    asm volatile("cp.async.commit_group;");                                   \
} while (0)

__global__ void __launch_bounds__(128) attn_mma_kernel()
{
    extern __shared__ __align__(16) char smd[];
    const uint32_t smb = smem_u32(smd);
    const int pairI = blockIdx.x >> 1;
    const int p = blockIdx.x & 1;
    const int b = blockIdx.y;
    const int tid  = threadIdx.x;
    const int lane = tid & 31;
    const int w    = tid >> 5;
    const int lg   = lane >> 2;
    const int lt   = lane & 3;
    const int wrow = w * 16;

    const int gg = lane >> 3, ii = lane & 7;
    const uint32_t lih =
        (uint32_t)((((gg >> 1) * 8) + ii) * 144 + (gg & 1) * 16);

    for (int tt = 0; tt < 2; tt++) {
        const int qt = tt ? (31 - pairI) : pairI;
        const int q0 = qt * 64;

        // Q fragments straight from global fp16 (pre-scaled)
        uint32_t qh[4][4];
        {
            const size_t qb = ((size_t)b * TT + q0) * HS;
            #pragma unroll
            for (int kk = 0; kk < 4; kk++) {
                int h0 = kk * 16 + 2 * lt;
                qh[kk][0] = *(const uint32_t*)&g_qh[qb + (wrow + lg) * HS + h0];
                qh[kk][1] = *(const uint32_t*)&g_qh[qb + (wrow + lg + 8) * HS + h0];
                qh[kk][2] = *(const uint32_t*)&g_qh[qb + (wrow + lg) * HS + h0 + 8];
                qh[kk][3] = *(const uint32_t*)&g_qh[qb + (wrow + lg + 8) * HS + h0 + 8];
            }
        }

        float O[8][4];
        #pragma unroll
        for (int j = 0; j < 8; j++)
            #pragma unroll
            for (int e = 0; e < 4; e++) O[j][e] = 0.0f;
        float m0 = -1e30f, m1 = -1e30f, l0 = 0.0f, l1 = 0.0f;

        const int nkt = (qt >= p) ? (((qt - p) >> 1) + 1) : 0;

        __syncthreads();                 // stage buffers free before reuse
        if (nkt > 0) LOADSTAGE(0, p);

        for (int i = 0; i < nkt; i++) {
            const int kt = p + 2 * i;
            const int st = i & 1;
            if (i) __syncthreads();      // compute i-1 done before buf reuse
            if (i + 1 < nkt) {
                LOADSTAGE(st ^ 1, kt + 2);
                asm volatile("cp.async.wait_group 1;");
            } else {
                asm volatile("cp.async.wait_group 0;");
            }
            __syncthreads();

            const uint32_t smKh = smb + st * STG;
            const uint32_t smVh = smKh + 9216;

            // ---- S = Q K^T (fp16 single-term), B-frags via ldmatrix.x4
            float s[8][4];
            #pragma unroll
            for (int j = 0; j < 8; j++)
                #pragma unroll
                for (int e = 0; e < 4; e++) s[j][e] = 0.0f;

            #pragma unroll
            for (int kk = 0; kk < 4; kk++) {
                #pragma unroll
                for (int jp = 0; jp < 4; jp++) {
                    uint32_t bh[4];
                    ldmx4(bh, smKh + lih + jp * 2304 + kk * 32);
                    mma16816h(s[2 * jp],     qh[kk], &bh[0]);
                    mma16816h(s[2 * jp + 1], qh[kk], &bh[2]);
                }
            }

            // ---- causal mask (diagonal tile only)
            if (kt == qt) {
                #pragma unroll
                for (int j = 0; j < 8; j++) {
                    int lc = j * 8 + 2 * lt;
                    int r0 = wrow + lg, r1 = r0 + 8;
                    if (lc > r0)     s[j][0] = -1e30f;
                    if (lc + 1 > r0) s[j][1] = -1e30f;
                    if (lc > r1)     s[j][2] = -1e30f;
                    if (lc + 1 > r1) s[j][3] = -1e30f;
                }
            }

            // ---- online softmax
            {
                float mx0 = -1e30f, mx1 = -1e30f;
                #pragma unroll
                for (int j = 0; j < 8; j++) {
                    mx0 = fmaxf(mx0, fmaxf(s[j][0], s[j][1]));
                    mx1 = fmaxf(mx1, fmaxf(s[j][2], s[j][3]));
                }
                #pragma unroll
                for (int o = 1; o <= 2; o <<= 1) {
                    mx0 = fmaxf(mx0, __shfl_xor_sync(0xffffffffu, mx0, o));
                    mx1 = fmaxf(mx1, __shfl_xor_sync(0xffffffffu, mx1, o));
                }
                float mn0 = fmaxf(m0, mx0), mn1 = fmaxf(m1, mx1);
                float al0 = __expf(m0 - mn0), al1 = __expf(m1 - mn1);
                float sum0 = 0.0f, sum1 = 0.0f;
                #pragma unroll
                for (int j = 0; j < 8; j++) {
                    s[j][0] = __expf(s[j][0] - mn0);
                    s[j][1] = __expf(s[j][1] - mn0);
                    s[j][2] = __expf(s[j][2] - mn1);
                    s[j][3] = __expf(s[j][3] - mn1);
                    sum0 += s[j][0] + s[j][1];
                    sum1 += s[j][2] + s[j][3];
                }
                #pragma unroll
                for (int o = 1; o <= 2; o <<= 1) {
                    sum0 += __shfl_xor_sync(0xffffffffu, sum0, o);
                    sum1 += __shfl_xor_sync(0xffffffffu, sum1, o);
                }
                l0 = l0 * al0 + sum0;
                l1 = l1 * al1 + sum1;
                m0 = mn0; m1 = mn1;
                #pragma unroll
                for (int j = 0; j < 8; j++) {
                    O[j][0] *= al0; O[j][1] *= al0;
                    O[j][2] *= al1; O[j][3] *= al1;
                }
            }

            // ---- pack P -> fp16
            uint32_t pp[8][2];
            #pragma unroll
            for (int j = 0; j < 8; j++) {
                __half2 a01 = __floats2half2_rn(s[j][0], s[j][1]);
                __half2 a23 = __floats2half2_rn(s[j][2], s[j][3]);
                pp[j][0] = *(uint32_t*)&a01;
                pp[j][1] = *(uint32_t*)&a23;
            }

            // ---- O += P @ V (fp16 single-term), V-frags via ldmatrix.x4
            #pragma unroll
            for (int jhp = 0; jhp < 4; jhp++) {
                #pragma unroll
                for (int kk = 0; kk < 4; kk++) {
                    uint32_t vh[4];
                    ldmx4(vh, smVh + lih + jhp * 2304 + kk * 32);
                    uint32_t aP[4] = {pp[2 * kk][0], pp[2 * kk][1],
                                      pp[2 * kk + 1][0], pp[2 * kk + 1][1]};
                    mma16816h(O[2 * jhp],     aP, &vh[0]);
                    mma16816h(O[2 * jhp + 1], aP, &vh[2]);
                }
            }
        }

        // ---- write partial (unnormalized O, m, l)
        {
            const size_t r0 = (size_t)b * TT + q0 + wrow + lg;
            float* po = g_pO + (size_t)p * PSTRIDE;
            #pragma unroll
            for (int jh = 0; jh < 8; jh++) {
                int hcol = jh * 8 + 2 * lt;
                *(float2*)&po[r0 * HS + hcol] = make_float2(O[jh][0], O[jh][1]);
                *(float2*)&po[(r0 + 8) * HS + hcol] = make_float2(O[jh][2], O[jh][3]);
            }
            if (lt == 0) {
                g_pm[p * ROWS + r0] = m0;
                g_pl[p * ROWS + r0] = l0;
                g_pm[p * ROWS + r0 + 8] = m1;
                g_pl[p * ROWS + r0 + 8] = l1;
            }
        }
    }
}

// ---------------------------------------------------------------------------
// Kernel 3: merge the two key-split partials (exact R7).
// ---------------------------------------------------------------------------
__global__ __launch_bounds__(256) void combine_kernel(float* __restrict__ out)
{
    int idx = blockIdx.x * 256 + threadIdx.x;    // 262144 total
    int row = idx >> 4;
    int h4 = (idx & 15) * 4;
    float m0 = g_pm[row], m1 = g_pm[ROWS + row];
    float l0 = g_pl[row], l1 = g_pl[ROWS + row];
    float M = fmaxf(m0, m1);
    float w0 = __expf(m0 - M), w1 = __expf(m1 - M);
    float inv = 1.0f / (w0 * l0 + w1 * l1);
    float4 a = *(const float4*)&g_pO[(size_t)row * HS + h4];
    float4 c = *(const float4*)&g_pO[PSTRIDE + (size_t)row * HS + h4];
    float4 o;
    o.x = (w0 * a.x + w1 * c.x) * inv;
    o.y = (w0 * a.y + w1 * c.y) * inv;
    o.z = (w0 * a.z + w1 * c.z) * inv;
    o.w = (w0 * a.w + w1 * c.w) * inv;
    *(float4*)&out[(size_t)row * HS + h4] = o;
}

// ---------------------------------------------------------------------------
extern "C" void kernel_launch(void* const* d_in, const int* in_sizes, int n_in,
                              void* d_out, int out_size)
{
    const float* X  = (const float*)d_in[0];
    const float* Wq = (const float*)d_in[1];
    const float* bq = (const float*)d_in[2];
    const float* Wk = (const float*)d_in[3];
    const float* bk = (const float*)d_in[4];
    const float* Wv = (const float*)d_in[5];
    const float* bv = (const float*)d_in[6];
    float* out = (float*)d_out;

    static int attr_set = 0;
    if (!attr_set) {
        cudaFuncSetAttribute(qkv_mma_kernel,
                             cudaFuncAttributeMaxDynamicSharedMemorySize,
                             SMEM_QKV);
        cudaFuncSetAttribute(attn_mma_kernel,
                             cudaFuncAttributeMaxDynamicSharedMemorySize,
                             2 * STG);
        attr_set = 1;
    }

    w_convert_kernel<<<192, 256>>>(Wq, Wk, Wv);
    qkv_mma_kernel<<<128, 256, SMEM_QKV>>>(X, bq, bk, bv);

    dim3 g2(32, BB);                       // pairs x parts, batches
    attn_mma_kernel<<<g2, 128, 2 * STG>>>();

    combine_kernel<<<ROWS * HS / 4 / 256, 256>>>(out);
}

// round 16
// speedup vs baseline: 1.4420x; 1.0191x over previous
#include <cuda_runtime.h>
#include <cuda_bf16.h>
#include <cuda_fp16.h>
#include <cstdint>

#define BB 8
#define TT 2048
#define EE 1024
#define HS 64
#define NTOT 192   // q(64) | k(64) | v(64)
#define ROWS (BB * TT)
#define PSTRIDE (BB * TT * HS)

// Preconverted operands (written by qkv epilogue)
__device__ __half g_qh[ROWS * HS];          // Q fp16, pre-scaled 0.125
__device__ __half g_kh[ROWS * HS];          // K fp16 [B*T][64]
__device__ __half g_vth[BB * HS * TT];      // V transposed [B][64h][2048t], fp16
// Weights fp16 (single precision level)
__device__ __half g_Wh[NTOT * EE];
// Attention partials (2 key-split parts)
__device__ float g_pO[2 * PSTRIDE];
__device__ float g_pm[2 * ROWS];
__device__ float g_pl[2 * ROWS];

// ---------------------------------------------------------------------------
// Helpers
// ---------------------------------------------------------------------------
__device__ __forceinline__ uint32_t smem_u32(const void* p) {
    uint32_t a;
    asm("{ .reg .u64 t; cvta.to.shared.u64 t, %1; cvt.u32.u64 %0, t; }"
        : "=r"(a) : "l"(p));
    return a;
}

__device__ __forceinline__ void cp16(uint32_t dst, const void* src) {
    asm volatile("cp.async.cg.shared.global [%0], [%1], 16;"
                 :: "r"(dst), "l"(src));
}

// fp16 mma, fp32 accum
__device__ __forceinline__ void mma16816h(float* c, const uint32_t* a,
                                          const uint32_t* b) {
    asm volatile(
        "mma.sync.aligned.m16n8k16.row.col.f32.f16.f16.f32 "
        "{%0,%1,%2,%3}, {%4,%5,%6,%7}, {%8,%9}, {%0,%1,%2,%3};"
        : "+f"(c[0]), "+f"(c[1]), "+f"(c[2]), "+f"(c[3])
        : "r"(a[0]), "r"(a[1]), "r"(a[2]), "r"(a[3]), "r"(b[0]), "r"(b[1]));
}

// ldmatrix x4 (non-trans, b16)
__device__ __forceinline__ void ldmx4(uint32_t* r, uint32_t addr) {
    asm volatile(
        "ldmatrix.sync.aligned.m8n8.x4.shared.b16 {%0,%1,%2,%3}, [%4];"
        : "=r"(r[0]), "=r"(r[1]), "=r"(r[2]), "=r"(r[3]) : "r"(addr));
}

// ---------------------------------------------------------------------------
// Kernel 0: convert concat(Wq,Wk,Wv) fp32 -> fp16, [192][1024]
// ---------------------------------------------------------------------------
__global__ __launch_bounds__(256) void w_convert_kernel(
    const float* __restrict__ Wq, const float* __restrict__ Wk,
    const float* __restrict__ Wv)
{
    int idx = blockIdx.x * 256 + threadIdx.x;
    int e4 = idx * 4;
    int n = e4 >> 10;
    int c = e4 & 1023;
    const float* src = (n < 64) ? &Wq[n * 1024 + c]
                     : (n < 128) ? &Wk[(n - 64) * 1024 + c]
                     : &Wv[(n - 128) * 1024 + c];
    float4 v = *(const float4*)src;
    __half h[4];
    h[0] = __float2half_rn(v.x);
    h[1] = __float2half_rn(v.y);
    h[2] = __float2half_rn(v.z);
    h[3] = __float2half_rn(v.w);
    *(uint2*)&g_Wh[e4] = *(uint2*)h;
}

// ---------------------------------------------------------------------------
// Kernel 1: QKV projection, fp16 single-term mma; frag loads via ldmatrix.
// A stage: 128 rows x 32 fp16, 80B stride.  B stage: 192 rows x 32 fp16,
// 80B stride (20-bank row stride -> conflict-free ldmatrix octets).
// ---------------------------------------------------------------------------
#define ASTRIDE 80
#define BOFF  10240
#define STAGE 25600
#define SMEM_QKV (2 * STAGE)

__global__ void __launch_bounds__(256) qkv_mma_kernel(
    const float* __restrict__ X,
    const float* __restrict__ bq, const float* __restrict__ bk,
    const float* __restrict__ bv)
{
    extern __shared__ __align__(128) char sm[];
    const uint32_t smb = smem_u32(sm);
    const int tid = threadIdx.x;
    const int lid = tid & 31;
    const int wid = tid >> 5;
    const int wm  = wid >> 2;
    const int wn  = wid & 3;
    const int lg  = lid >> 2;
    const int lt  = lid & 3;
    const int m0  = blockIdx.x * 128;
    const int arow = tid >> 1;
    const int akh  = tid & 1;

    // ldmatrix lane-offsets (gg selects which 8x8 matrix this lane feeds)
    const int gg = lid >> 3, ii = lid & 7;
    const uint32_t aoff = (uint32_t)((((gg & 1) * 8) + ii) * 80 + (gg >> 1) * 16);
    const uint32_t boff = (uint32_t)((((gg >> 1) * 8) + ii) * 80 + (gg & 1) * 16);

    float acc[4][6][4];
    #pragma unroll
    for (int t = 0; t < 4; t++)
        #pragma unroll
        for (int u = 0; u < 6; u++)
            #pragma unroll
            for (int r = 0; r < 4; r++) acc[t][u][r] = 0.0f;

    float4 xr[4];

    // ---- prologue: chunk 0
    {
        const float* xp = &X[(size_t)(m0 + arow) * EE + akh * 16];
        #pragma unroll
        for (int p = 0; p < 4; p++) xr[p] = *(const float4*)&xp[p * 4];
        #pragma unroll
        for (int j = 0; j < 3; j++) {
            int idx = j * 256 + tid;          // 0..767
            int n = idx >> 2, u = idx & 3;
            cp16(smb + BOFF + n * 80 + u * 16, g_Wh + n * EE + u * 8);
        }
        asm volatile("cp.async.commit_group;");
        {
            __half2 hh[8];
            #pragma unroll
            for (int p = 0; p < 4; p++) {
                hh[2 * p]     = __floats2half2_rn(xr[p].x, xr[p].y);
                hh[2 * p + 1] = __floats2half2_rn(xr[p].z, xr[p].w);
            }
            *(uint4*)(sm + arow * ASTRIDE + akh * 32)      = *(uint4*)&hh[0];
            *(uint4*)(sm + arow * ASTRIDE + akh * 32 + 16) = *(uint4*)&hh[4];
        }
        asm volatile("cp.async.wait_group 0;");
        __syncthreads();
    }

    for (int c = 0; c < 32; c++) {
        const int cb = c & 1;
        const int nb = (c + 1) & 1;
        if (c < 31) {
            const int k0 = (c + 1) * 32;
            const float* xp = &X[(size_t)(m0 + arow) * EE + k0 + akh * 16];
            #pragma unroll
            for (int p = 0; p < 4; p++) xr[p] = *(const float4*)&xp[p * 4];
            #pragma unroll
            for (int j = 0; j < 3; j++) {
                int idx = j * 256 + tid;
                int n = idx >> 2, u = idx & 3;
                cp16(smb + nb * STAGE + BOFF + n * 80 + u * 16,
                     g_Wh + n * EE + k0 + u * 8);
            }
            asm volatile("cp.async.commit_group;");
        }

        // ---- compute chunk c (two k16 steps), frags via ldmatrix.x4
        const uint32_t abU = smb + cb * STAGE;
        const uint32_t bbU = abU + BOFF;
        #pragma unroll
        for (int h = 0; h < 2; h++) {
            uint32_t af[4][4], bf[6][2];
            #pragma unroll
            for (int t = 0; t < 4; t++)
                ldmx4(af[t], abU + (uint32_t)((wm * 64 + t * 16) * 80 + h * 32) + aoff);
            #pragma unroll
            for (int up = 0; up < 3; up++) {
                uint32_t bm[4];
                ldmx4(bm, bbU + (uint32_t)((wn * 48 + up * 16) * 80 + h * 32) + boff);
                bf[2 * up][0]     = bm[0];
                bf[2 * up][1]     = bm[1];
                bf[2 * up + 1][0] = bm[2];
                bf[2 * up + 1][1] = bm[3];
            }
            #pragma unroll
            for (int t = 0; t < 4; t++)
                #pragma unroll
                for (int u = 0; u < 6; u++)
                    mma16816h(acc[t][u], af[t], bf[u]);
        }

        if (c < 31) {
            __half2 hh[8];
            #pragma unroll
            for (int p = 0; p < 4; p++) {
                hh[2 * p]     = __floats2half2_rn(xr[p].x, xr[p].y);
                hh[2 * p + 1] = __floats2half2_rn(xr[p].z, xr[p].w);
            }
            *(uint4*)(sm + nb * STAGE + arow * ASTRIDE + akh * 32)      = *(uint4*)&hh[0];
            *(uint4*)(sm + nb * STAGE + arow * ASTRIDE + akh * 32 + 16) = *(uint4*)&hh[4];
            asm volatile("cp.async.wait_group 0;");
        }
        __syncthreads();
    }

    // ---- epilogue: + bias; Q/K -> fp16; V -> fp16 via smem transpose
    __half* VtSh = (__half*)sm;                  // [64h][128 rl]

    #pragma unroll
    for (int t = 0; t < 4; t++) {
        int rl = wm * 64 + t * 16 + lg;
        size_t rg = (size_t)(m0 + rl);
        #pragma unroll
        for (int u = 0; u < 6; u++) {
            int n = wn * 48 + u * 8 + lt * 2;
            const float* barr; int col; int kind;
            if (n < 64)       { col = n;       barr = bq; kind = 0; }
            else if (n < 128) { col = n - 64;  barr = bk; kind = 1; }
            else              { col = n - 128; barr = bv; kind = 2; }
            float b0 = __ldg(&barr[col]), b1 = __ldg(&barr[col + 1]);
            float v00 = acc[t][u][0] + b0;
            float v01 = acc[t][u][1] + b1;
            float v10 = acc[t][u][2] + b0;
            float v11 = acc[t][u][3] + b1;
            if (kind == 0) {
                v00 *= 0.125f; v01 *= 0.125f; v10 *= 0.125f; v11 *= 0.125f;
            }
            if (kind < 2) {
                __half* dh = kind ? g_kh : g_qh;
                __half2 h0p = __floats2half2_rn(v00, v01);
                __half2 h1p = __floats2half2_rn(v10, v11);
                *(uint32_t*)&dh[rg * HS + col]       = *(uint32_t*)&h0p;
                *(uint32_t*)&dh[(rg + 8) * HS + col] = *(uint32_t*)&h1p;
            } else {
                VtSh[col * 128 + rl]           = __float2half_rn(v00);
                VtSh[(col + 1) * 128 + rl]     = __float2half_rn(v01);
                VtSh[col * 128 + rl + 8]       = __float2half_rn(v10);
                VtSh[(col + 1) * 128 + rl + 8] = __float2half_rn(v11);
            }
        }
    }
    __syncthreads();
    {
        int bbb = m0 >> 11, t0 = m0 & 2047;
        #pragma unroll
        for (int q = 0; q < 4; q++) {
            int idx = q * 256 + tid;
            int h = idx >> 4, cc = idx & 15;
            __half* dst = g_vth + ((size_t)(bbb * HS + h)) * TT + t0 + cc * 8;
            *(uint4*)dst = *(const uint4*)(VtSh + h * 128 + cc * 8);
        }
    }
}

// ---------------------------------------------------------------------------
// Kernel 2: causal flash attention (exact R15).
// ---------------------------------------------------------------------------
#define STG 18432

#define LOADSTAGE(st_, kt_) do {                                              \
    uint32_t sb_ = smb + (st_) * STG;                                         \
    size_t kbase_ = ((size_t)b * TT + (size_t)(kt_) * 64) * HS;               \
    size_t vbase_ = (size_t)b * (HS * TT) + (size_t)(kt_) * 64;               \
    _Pragma("unroll")                                                         \
    for (int q_ = 0; q_ < 4; q_++) {                                          \
        int idx_ = q_ * 128 + tid;                                            \
        int r_ = idx_ >> 3, c_ = idx_ & 7;                                    \
        cp16(sb_ + r_ * 144 + c_ * 16,         g_kh + kbase_ + r_ * HS + c_ * 8);  \
        cp16(sb_ + 9216 + r_ * 144 + c_ * 16,  g_vth + vbase_ + (size_t)r_ * TT + c_ * 8); \
    }                                                                         \
    asm volatile("cp.async.commit_group;");                                   \
} while (0)

__global__ void __launch_bounds__(128) attn_mma_kernel()
{
    extern __shared__ __align__(16) char smd[];
    const uint32_t smb = smem_u32(smd);
    const int pairI = blockIdx.x >> 1;
    const int p = blockIdx.x & 1;
    const int b = blockIdx.y;
    const int tid  = threadIdx.x;
    const int lane = tid & 31;
    const int w    = tid >> 5;
    const int lg   = lane >> 2;
    const int lt   = lane & 3;
    const int wrow = w * 16;

    const int gg = lane >> 3, ii = lane & 7;
    const uint32_t lih =
        (uint32_t)((((gg >> 1) * 8) + ii) * 144 + (gg & 1) * 16);

    for (int tt = 0; tt < 2; tt++) {
        const int qt = tt ? (31 - pairI) : pairI;
        const int q0 = qt * 64;

        // Q fragments straight from global fp16 (pre-scaled)
        uint32_t qh[4][4];
        {
            const size_t qb = ((size_t)b * TT + q0) * HS;
            #pragma unroll
            for (int kk = 0; kk < 4; kk++) {
                int h0 = kk * 16 + 2 * lt;
                qh[kk][0] = *(const uint32_t*)&g_qh[qb + (wrow + lg) * HS + h0];
                qh[kk][1] = *(const uint32_t*)&g_qh[qb + (wrow + lg + 8) * HS + h0];
                qh[kk][2] = *(const uint32_t*)&g_qh[qb + (wrow + lg) * HS + h0 + 8];
                qh[kk][3] = *(const uint32_t*)&g_qh[qb + (wrow + lg + 8) * HS + h0 + 8];
            }
        }

        float O[8][4];
        #pragma unroll
        for (int j = 0; j < 8; j++)
            #pragma unroll
            for (int e = 0; e < 4; e++) O[j][e] = 0.0f;
        float m0 = -1e30f, m1 = -1e30f, l0 = 0.0f, l1 = 0.0f;

        const int nkt = (qt >= p) ? (((qt - p) >> 1) + 1) : 0;

        __syncthreads();                 // stage buffers free before reuse
        if (nkt > 0) LOADSTAGE(0, p);

        for (int i = 0; i < nkt; i++) {
            const int kt = p + 2 * i;
            const int st = i & 1;
            if (i) __syncthreads();      // compute i-1 done before buf reuse
            if (i + 1 < nkt) {
                LOADSTAGE(st ^ 1, kt + 2);
                asm volatile("cp.async.wait_group 1;");
            } else {
                asm volatile("cp.async.wait_group 0;");
            }
            __syncthreads();

            const uint32_t smKh = smb + st * STG;
            const uint32_t smVh = smKh + 9216;

            // ---- S = Q K^T (fp16 single-term), B-frags via ldmatrix.x4
            float s[8][4];
            #pragma unroll
            for (int j = 0; j < 8; j++)
                #pragma unroll
                for (int e = 0; e < 4; e++) s[j][e] = 0.0f;

            #pragma unroll
            for (int kk = 0; kk < 4; kk++) {
                #pragma unroll
                for (int jp = 0; jp < 4; jp++) {
                    uint32_t bh[4];
                    ldmx4(bh, smKh + lih + jp * 2304 + kk * 32);
                    mma16816h(s[2 * jp],     qh[kk], &bh[0]);
                    mma16816h(s[2 * jp + 1], qh[kk], &bh[2]);
                }
            }

            // ---- causal mask (diagonal tile only)
            if (kt == qt) {
                #pragma unroll
                for (int j = 0; j < 8; j++) {
                    int lc = j * 8 + 2 * lt;
                    int r0 = wrow + lg, r1 = r0 + 8;
                    if (lc > r0)     s[j][0] = -1e30f;
                    if (lc + 1 > r0) s[j][1] = -1e30f;
                    if (lc > r1)     s[j][2] = -1e30f;
                    if (lc + 1 > r1) s[j][3] = -1e30f;
                }
            }

            // ---- online softmax
            {
                float mx0 = -1e30f, mx1 = -1e30f;
                #pragma unroll
                for (int j = 0; j < 8; j++) {
                    mx0 = fmaxf(mx0, fmaxf(s[j][0], s[j][1]));
                    mx1 = fmaxf(mx1, fmaxf(s[j][2], s[j][3]));
                }
                #pragma unroll
                for (int o = 1; o <= 2; o <<= 1) {
                    mx0 = fmaxf(mx0, __shfl_xor_sync(0xffffffffu, mx0, o));
                    mx1 = fmaxf(mx1, __shfl_xor_sync(0xffffffffu, mx1, o));
                }
                float mn0 = fmaxf(m0, mx0), mn1 = fmaxf(m1, mx1);
                float al0 = __expf(m0 - mn0), al1 = __expf(m1 - mn1);
                float sum0 = 0.0f, sum1 = 0.0f;
                #pragma unroll
                for (int j = 0; j < 8; j++) {
                    s[j][0] = __expf(s[j][0] - mn0);
                    s[j][1] = __expf(s[j][1] - mn0);
                    s[j][2] = __expf(s[j][2] - mn1);
                    s[j][3] = __expf(s[j][3] - mn1);
                    sum0 += s[j][0] + s[j][1];
                    sum1 += s[j][2] + s[j][3];
                }
                #pragma unroll
                for (int o = 1; o <= 2; o <<= 1) {
                    sum0 += __shfl_xor_sync(0xffffffffu, sum0, o);
                    sum1 += __shfl_xor_sync(0xffffffffu, sum1, o);
                }
                l0 = l0 * al0 + sum0;
                l1 = l1 * al1 + sum1;
                m0 = mn0; m1 = mn1;
                #pragma unroll
                for (int j = 0; j < 8; j++) {
                    O[j][0] *= al0; O[j][1] *= al0;
                    O[j][2] *= al1; O[j][3] *= al1;
                }
            }

            // ---- pack P -> fp16
            uint32_t pp[8][2];
            #pragma unroll
            for (int j = 0; j < 8; j++) {
                __half2 a01 = __floats2half2_rn(s[j][0], s[j][1]);
                __half2 a23 = __floats2half2_rn(s[j][2], s[j][3]);
                pp[j][0] = *(uint32_t*)&a01;
                pp[j][1] = *(uint32_t*)&a23;
            }

            // ---- O += P @ V (fp16 single-term), V-frags via ldmatrix.x4
            #pragma unroll
            for (int jhp = 0; jhp < 4; jhp++) {
                #pragma unroll
                for (int kk = 0; kk < 4; kk++) {
                    uint32_t vh[4];
                    ldmx4(vh, smVh + lih + jhp * 2304 + kk * 32);
                    uint32_t aP[4] = {pp[2 * kk][0], pp[2 * kk][1],
                                      pp[2 * kk + 1][0], pp[2 * kk + 1][1]};
                    mma16816h(O[2 * jhp],     aP, &vh[0]);
                    mma16816h(O[2 * jhp + 1], aP, &vh[2]);
                }
            }
        }

        // ---- write partial (unnormalized O, m, l)
        {
            const size_t r0 = (size_t)b * TT + q0 + wrow + lg;
            float* po = g_pO + (size_t)p * PSTRIDE;
            #pragma unroll
            for (int jh = 0; jh < 8; jh++) {
                int hcol = jh * 8 + 2 * lt;
                *(float2*)&po[r0 * HS + hcol] = make_float2(O[jh][0], O[jh][1]);
                *(float2*)&po[(r0 + 8) * HS + hcol] = make_float2(O[jh][2], O[jh][3]);
            }
            if (lt == 0) {
                g_pm[p * ROWS + r0] = m0;
                g_pl[p * ROWS + r0] = l0;
                g_pm[p * ROWS + r0 + 8] = m1;
                g_pl[p * ROWS + r0 + 8] = l1;
            }
        }
    }
}

// ---------------------------------------------------------------------------
// Kernel 3: merge the two key-split partials (exact R7).
// ---------------------------------------------------------------------------
__global__ __launch_bounds__(256) void combine_kernel(float* __restrict__ out)
{
    int idx = blockIdx.x * 256 + threadIdx.x;    // 262144 total
    int row = idx >> 4;
    int h4 = (idx & 15) * 4;
    float m0 = g_pm[row], m1 = g_pm[ROWS + row];
    float l0 = g_pl[row], l1 = g_pl[ROWS + row];
    float M = fmaxf(m0, m1);
    float w0 = __expf(m0 - M), w1 = __expf(m1 - M);
    float inv = 1.0f / (w0 * l0 + w1 * l1);
    float4 a = *(const float4*)&g_pO[(size_t)row * HS + h4];
    float4 c = *(const float4*)&g_pO[PSTRIDE + (size_t)row * HS + h4];
    float4 o;
    o.x = (w0 * a.x + w1 * c.x) * inv;
    o.y = (w0 * a.y + w1 * c.y) * inv;
    o.z = (w0 * a.z + w1 * c.z) * inv;
    o.w = (w0 * a.w + w1 * c.w) * inv;
    *(float4*)&out[(size_t)row * HS + h4] = o;
}

// ---------------------------------------------------------------------------
extern "C" void kernel_launch(void* const* d_in, const int* in_sizes, int n_in,
                              void* d_out, int out_size)
{
    const float* X  = (const float*)d_in[0];
    const float* Wq = (const float*)d_in[1];
    const float* bq = (const float*)d_in[2];
    const float* Wk = (const float*)d_in[3];
    const float* bk = (const float*)d_in[4];
    const float* Wv = (const float*)d_in[5];
    const float* bv = (const float*)d_in[6];
    float* out = (float*)d_out;

    static int attr_set = 0;
    if (!attr_set) {
        cudaFuncSetAttribute(qkv_mma_kernel,
                             cudaFuncAttributeMaxDynamicSharedMemorySize,
                             SMEM_QKV);
        cudaFuncSetAttribute(attn_mma_kernel,
                             cudaFuncAttributeMaxDynamicSharedMemorySize,
                             2 * STG);
        attr_set = 1;
    }

    w_convert_kernel<<<192, 256>>>(Wq, Wk, Wv);
    qkv_mma_kernel<<<128, 256, SMEM_QKV>>>(X, bq, bk, bv);

    dim3 g2(32, BB);                       // pairs x parts, batches
    attn_mma_kernel<<<g2, 128, 2 * STG>>>();

    combine_kernel<<<ROWS * HS / 4 / 256, 256>>>(out);
}